// round 1
// baseline (speedup 1.0000x reference)
#include <cuda_runtime.h>

#define Bb 2
#define Ii 1024
#define Jj 1024
#define Cc 64
#define THREADS 128
#define JT 128
#define NT (Jj / JT)

__device__ __forceinline__ float tanh_apx(float x) {
    float r;
    asm("tanh.approx.f32 %0, %1;" : "=f"(r) : "f"(x));
    return r;
}

__global__ __launch_bounds__(THREADS, 3)
void attn_mlp_kernel(const float* __restrict__ Q, const float* __restrict__ K,
                     const float* __restrict__ bias, const float* __restrict__ mask,
                     float* __restrict__ out, float* __restrict__ attn)
{
    // K tile: 128 rows x 17 float4 (68-float padded stride -> conflict-free LDS.128)
    __shared__ float4 ksm[JT * 17];
    __shared__ float4 qs[Cc / 4], bs[Cc / 4];
    __shared__ float cred[4];

    const int row = blockIdx.x;          // b*I + i
    const int b   = row >> 10;           // I = 1024
    const int tid = threadIdx.x;

    // Prescale: qhat = 0.5*Q_row, bhat = 0.5*bias  (sigmoid(x) = 0.5 + 0.5*tanh(x/2))
    if (tid < Cc) {
        ((float*)qs)[tid] = 0.5f * Q[(size_t)row * Cc + tid];
        ((float*)bs)[tid] = 0.5f * bias[tid];
    }

    float sacc[Cc];
#pragma unroll
    for (int c = 0; c < Cc; ++c) sacc[c] = 0.f;
    float cnt = 0.f;

    const float4* Kg   = (const float4*)K + (size_t)b * Jj * (Cc / 4);
    const float*  mrow = mask + (size_t)row * Jj;
    float*        arow = attn + (size_t)row * Jj;

    for (int tile = 0; tile < NT; ++tile) {
        __syncthreads();   // also covers qs/bs init on tile 0, and tile reuse
        // Stage K tile into smem (coalesced float4 reads, padded rows)
#pragma unroll
        for (int u = 0; u < (JT * (Cc / 4)) / THREADS; ++u) {   // 16 iters
            int f  = u * THREADS + tid;
            int jr = f >> 4;
            int c4 = f & 15;
            ksm[jr * 17 + c4] = Kg[(size_t)(tile * JT + jr) * (Cc / 4) + c4];
        }
        __syncthreads();

        const int   j = tile * JT + tid;
        const float m = mrow[j];
        float dot = 0.f;
#pragma unroll
        for (int c4 = 0; c4 < Cc / 4; ++c4) {
            float4 kv = ksm[tid * 17 + c4];
            float4 qv = qs[c4];
            float4 bv = bs[c4];
            float h;
            h = qv.x * kv.x; dot += h; sacc[4*c4+0] += m * tanh_apx(h + bv.x);
            h = qv.y * kv.y; dot += h; sacc[4*c4+1] += m * tanh_apx(h + bv.y);
            h = qv.z * kv.z; dot += h; sacc[4*c4+2] += m * tanh_apx(h + bv.z);
            h = qv.w * kv.w; dot += h; sacc[4*c4+3] += m * tanh_apx(h + bv.w);
        }
        cnt += m;
        // dot = 0.5 * (Q.K), so attention_logits = mask * 2*dot (exact fp32 path)
        arow[j] = (dot + dot) * m;
    }

    // ---- Block reductions ----
    __syncthreads();                   // everyone done reading ksm
    float* sred = (float*)ksm;         // reuse: 64 * 129 floats = 33024 B <= 34816 B
#pragma unroll
    for (int c = 0; c < Cc; ++c)
        sred[c * 129 + tid] = sacc[c]; // pad 129 -> conflict-free both directions

    // mask-count reduction
    for (int o = 16; o > 0; o >>= 1)
        cnt += __shfl_xor_sync(0xffffffffu, cnt, o);
    if ((tid & 31) == 0) cred[tid >> 5] = cnt;
    __syncthreads();

    if (tid < Cc) {
        float ct = cred[0] + cred[1] + cred[2] + cred[3];
        float s = 0.f;
        const float* p = sred + tid * 129;
#pragma unroll 8
        for (int t = 0; t < THREADS; ++t) s += p[t];
        // output = (0.5*cnt + 0.5*sum(m*tanh)) / cnt = 0.5 + 0.5*s/cnt
        out[(size_t)row * Cc + tid] = 0.5f + 0.5f * s / ct;
    }
}

extern "C" void kernel_launch(void* const* d_in, const int* in_sizes, int n_in,
                              void* d_out, int out_size)
{
    const float* Q    = (const float*)d_in[0];
    const float* K    = (const float*)d_in[1];
    const float* bias = (const float*)d_in[2];
    const float* mask = (const float*)d_in[3];
    float* out  = (float*)d_out;                       // [B, I, C] first
    float* attn = out + (size_t)Bb * Ii * Cc;          // then [B, I, J]
    attn_mlp_kernel<<<Bb * Ii, THREADS>>>(Q, K, bias, mask, out, attn);
}

// round 2
// speedup vs baseline: 1.7268x; 1.7268x over previous
#include <cuda_runtime.h>

#define THREADS 128
#define Jt 32
#define NT 32          // 1024 / Jt

typedef unsigned long long u64;

__device__ __forceinline__ float tanh_apx(float x) {
    float r; asm("tanh.approx.f32 %0, %1;" : "=f"(r) : "f"(x)); return r;
}
#define FMA2(d,a,b,c)  asm("fma.rn.f32x2 %0, %1, %2, %3;" : "=l"(d) : "l"(a), "l"(b), "l"(c))
#define PACK2(d,x,y)   asm("mov.b64 %0, {%1,%2};" : "=l"(d) : "f"(x), "f"(y))
#define UNPACK2(x,y,d) asm("mov.b64 {%0,%1}, %2;" : "=f"(x), "=f"(y) : "l"(d))

__global__ __launch_bounds__(THREADS, 3)
void attn_mlp_kernel(const float* __restrict__ Q, const float* __restrict__ K,
                     const float* __restrict__ bias, const float* __restrict__ mask,
                     float* __restrict__ out, float* __restrict__ attn)
{
    __shared__ float4 ksm[2][Jt * 17];   // double-buffered K tile, pad 17 -> conflict-free
    __shared__ float  red[512];
    __shared__ float  cbuf[2][4];

    const int tid = threadIdx.x;
    const int w   = tid >> 5, l = tid & 31;
    const int jl  = w * 8 + (l & 7);     // j within tile (0..31)
    const int cg  = l >> 3;              // channel group (16 ch each)

    const int row0 = blockIdx.x * 2;     // two i-rows per block, same b
    const int b    = row0 >> 10;

    // q (prescaled by 0.5 for sigmoid = 0.5 + 0.5*tanh(x/2)) and bias, packed f32x2
    u64 q20[8], q21[8], b2[8], s20[8], s21[8];
    {
        const float* q0p = Q + (size_t)row0 * 64 + cg * 16;
        const float* q1p = q0p + 64;
        const float* bp  = bias + cg * 16;
#pragma unroll
        for (int p = 0; p < 8; ++p) {
            PACK2(q20[p], 0.5f * q0p[2*p], 0.5f * q0p[2*p+1]);
            PACK2(q21[p], 0.5f * q1p[2*p], 0.5f * q1p[2*p+1]);
            PACK2(b2[p],  0.5f * bp[2*p],  0.5f * bp[2*p+1]);
            s20[p] = 0ull; s21[p] = 0ull;
        }
    }
    float cnt0 = 0.f, cnt1 = 0.f;

    const float4* Kg  = (const float4*)K + (size_t)b * 1024 * 16;
    const float*  m0p = mask + (size_t)row0 * 1024;
    const float*  m1p = m0p + 1024;
    float*        a0p = attn + (size_t)row0 * 1024;
    float*        a1p = a0p + 1024;

    // prefetch tile 0 into registers
    float4 kpre[4];
#pragma unroll
    for (int u = 0; u < 4; ++u) {
        int f = u * 128 + tid;
        kpre[u] = Kg[(size_t)(f >> 4) * 16 + (f & 15)];
    }

    int buf = 0;
    for (int tile = 0; tile < NT; ++tile) {
        // commit prefetched tile to smem
#pragma unroll
        for (int u = 0; u < 4; ++u) {
            int f = u * 128 + tid;
            ksm[buf][(f >> 4) * 17 + (f & 15)] = kpre[u];
        }
        __syncthreads();

        // prefetch next tile (LDG latency overlapped with compute below)
        if (tile + 1 < NT) {
#pragma unroll
            for (int u = 0; u < 4; ++u) {
                int f = u * 128 + tid;
                kpre[u] = Kg[(size_t)((tile + 1) * Jt + (f >> 4)) * 16 + (f & 15)];
            }
        }

        u64 k2[8];
#pragma unroll
        for (int p4 = 0; p4 < 4; ++p4) {
            float4 kv = ksm[buf][jl * 17 + cg * 4 + p4];
            PACK2(k2[2*p4],   kv.x, kv.y);
            PACK2(k2[2*p4+1], kv.z, kv.w);
        }
        const int   j  = tile * Jt + jl;
        const float m0 = m0p[j], m1 = m1p[j];
        u64 m20, m21; PACK2(m20, m0, m0); PACK2(m21, m1, m1);
        u64 dp0 = 0ull, dp1 = 0ull;

#pragma unroll
        for (int p = 0; p < 8; ++p) {
            u64 l2, t2; float la, lb;
            FMA2(l2, q20[p], k2[p], b2[p]);
            FMA2(dp0, q20[p], k2[p], dp0);
            UNPACK2(la, lb, l2);
            PACK2(t2, tanh_apx(la), tanh_apx(lb));
            FMA2(s20[p], m20, t2, s20[p]);

            FMA2(l2, q21[p], k2[p], b2[p]);
            FMA2(dp1, q21[p], k2[p], dp1);
            UNPACK2(la, lb, l2);
            PACK2(t2, tanh_apx(la), tanh_apx(lb));
            FMA2(s21[p], m21, t2, s21[p]);
        }
        if (cg == 0) { cnt0 += m0; cnt1 += m1; }

        // attention logits: dot was over prescaled q -> attn = 2*dot*mask (exact fp32 path)
        float dx, dy;
        UNPACK2(dx, dy, dp0); float d0 = dx + dy;
        UNPACK2(dx, dy, dp1); float d1 = dx + dy;
        d0 += __shfl_xor_sync(~0u, d0, 8);
        d0 += __shfl_xor_sync(~0u, d0, 16);
        d1 += __shfl_xor_sync(~0u, d1, 8);
        d1 += __shfl_xor_sync(~0u, d1, 16);
        if (cg == 0) {
            a0p[j] = (d0 + d0) * m0;
            a1p[j] = (d1 + d1) * m1;
        }
        buf ^= 1;   // next STS targets the other buffer -> one sync per tile suffices
    }

    // ---- final reductions ----
    // sacc: reduce over the 8 j-lanes sharing this cg within the warp
#pragma unroll
    for (int p = 0; p < 8; ++p) {
        float x0, y0, x1, y1;
        UNPACK2(x0, y0, s20[p]); UNPACK2(x1, y1, s21[p]);
#pragma unroll
        for (int o = 1; o <= 4; o <<= 1) {
            x0 += __shfl_xor_sync(~0u, x0, o);
            y0 += __shfl_xor_sync(~0u, y0, o);
            x1 += __shfl_xor_sync(~0u, x1, o);
            y1 += __shfl_xor_sync(~0u, y1, o);
        }
        if ((l & 7) == 0) {
            float* rp = red + w * 128 + cg * 32;
            rp[2*p]          = x0;
            rp[2*p + 1]      = y0;
            rp[16 + 2*p]     = x1;
            rp[16 + 2*p + 1] = y1;
        }
    }
    // mask counts (held by cg==0 lanes, i.e. lanes 0..7 of each warp)
    for (int o = 1; o <= 4; o <<= 1) {
        cnt0 += __shfl_xor_sync(~0u, cnt0, o);
        cnt1 += __shfl_xor_sync(~0u, cnt1, o);
    }
    if (l == 0) { cbuf[0][w] = cnt0; cbuf[1][w] = cnt1; }
    __syncthreads();

    // one output element per thread: (row r, channel ch)
    {
        const int r  = tid >> 6;
        const int ch = tid & 63;
        float ct = cbuf[r][0] + cbuf[r][1] + cbuf[r][2] + cbuf[r][3];
        float s  = 0.f;
#pragma unroll
        for (int ww = 0; ww < 4; ++ww)
            s += red[ww * 128 + (ch >> 4) * 32 + r * 16 + (ch & 15)];
        out[(size_t)(row0 + r) * 64 + ch] = 0.5f + 0.5f * s / ct;
    }
}

extern "C" void kernel_launch(void* const* d_in, const int* in_sizes, int n_in,
                              void* d_out, int out_size)
{
    const float* Q    = (const float*)d_in[0];
    const float* K    = (const float*)d_in[1];
    const float* bias = (const float*)d_in[2];
    const float* mask = (const float*)d_in[3];
    float* out  = (float*)d_out;                       // [B, I, C]
    float* attn = out + (size_t)2 * 1024 * 64;         // [B, I, J]
    attn_mlp_kernel<<<1024, THREADS>>>(Q, K, bias, mask, out, attn);
}